// round 10
// baseline (speedup 1.0000x reference)
#include <cuda_runtime.h>
#include <cuda_fp16.h>
#include <cstdint>
#include <cstddef>

#define DIM     512
#define BATCH   8
#define SEQ     4096
#define M_TOTAL (BATCH * SEQ)   // 32768

// ---------------------------------------------------------------------------
// Scratch (__device__ globals; no allocation allowed)
// ---------------------------------------------------------------------------
__device__ __half  g_uh[(size_t)M_TOTAL * DIM];   // u fp16 (GEMM2 out)
__device__ __half  g_qh[(size_t)M_TOTAL * DIM];   // q -> qn (fp16, in place)
__device__ __half  g_kh[(size_t)M_TOTAL * DIM];   // k -> kn (fp16, in place)
__device__ __half  g_wT[3u * DIM * DIM];          // wq^T, wk^T, wf^T fp16 (concat rows)
__device__ __half  g_wpT[(size_t)BATCH * DIM * DIM]; // (diag(gq_b) wp)^T fp16
__device__ float   g_gq[BATCH * DIM];

// ---------------------------------------------------------------------------
// helpers
// ---------------------------------------------------------------------------
__device__ __forceinline__ uint32_t smem_u32(const void* p) {
    uint32_t a;
    asm("{ .reg .u64 t; cvta.to.shared.u64 t, %1; cvt.u32.u64 %0, t; }" : "=r"(a) : "l"(p));
    return a;
}
__device__ __forceinline__ uint32_t swz(uint32_t o) { return o ^ ((o >> 3) & 0x70); }

__device__ __forceinline__ uint32_t h2_bits(__half2 v) {
    uint32_t u;
    *reinterpret_cast<__half2*>(&u) = v;
    return u;
}

__device__ __forceinline__ void cp16(uint32_t s, const void* g) {
    asm volatile("cp.async.cg.shared.global [%0], [%1], 16;\n" :: "r"(s), "l"(g));
}
#define CP_COMMIT() asm volatile("cp.async.commit_group;\n" ::: "memory")
#define CP_WAIT1()  asm volatile("cp.async.wait_group 1;\n" ::: "memory")

__device__ __forceinline__ void ldsm4(uint32_t* r, uint32_t addr) {
    asm volatile("ldmatrix.sync.aligned.m8n8.x4.shared.b16 {%0,%1,%2,%3}, [%4];\n"
                 : "=r"(r[0]), "=r"(r[1]), "=r"(r[2]), "=r"(r[3]) : "r"(addr));
}
__device__ __forceinline__ void mma16816(float* d, const uint32_t* a, const uint32_t* b) {
    asm volatile(
        "mma.sync.aligned.m16n8k16.row.col.f32.f16.f16.f32 "
        "{%0,%1,%2,%3}, {%4,%5,%6,%7}, {%8,%9}, {%0,%1,%2,%3};\n"
        : "+f"(d[0]), "+f"(d[1]), "+f"(d[2]), "+f"(d[3])
        : "r"(a[0]), "r"(a[1]), "r"(a[2]), "r"(a[3]), "r"(b[0]), "r"(b[1]));
}

// ===========================================================================
// GEMM1 (fused fp32->fp16 A conversion):
//   [q | k] = x @ [wq^T | wk^T]^T + [bq | bk]
// A = x fp32 [M,512] loaded LDG->cvt->STS. B = wT fp16 K-major [1024,512].
// CTA 128M x 256N, 512 threads = 16 warps (2M x 8N of 64x32 warp tiles).
// 3-stage: A16 16KB + B 32KB per stage = 48KB -> 144KB, occ 1 (16 warps/SM).
// N-tiles 0,1 -> qh/bq ; 2,3 -> kh/bk.
// ===========================================================================
#define G1_STAGE   49152u
#define G1_SMEM    (3u * G1_STAGE)   // 147456

__device__ __forceinline__ void g1_ldgA(const float* __restrict__ x,
                                        int m0, int c, int t, float* ar)
{
    const int g  = t & 7;            // 8-half group within row
    const int rb = t >> 3;           // 0..63
    const int k0 = c * 64;
#pragma unroll
    for (int it = 0; it < 2; it++) {
        const float* p = x + (size_t)(m0 + it * 64 + rb) * DIM + k0 + g * 8;
        *reinterpret_cast<float4*>(ar + it * 8)     = *reinterpret_cast<const float4*>(p);
        *reinterpret_cast<float4*>(ar + it * 8 + 4) = *reinterpret_cast<const float4*>(p + 4);
    }
}

__device__ __forceinline__ void g1_cvt_sts(uint32_t sA, int t, const float* ar)
{
    const int g  = t & 7;
    const int rb = t >> 3;
#pragma unroll
    for (int it = 0; it < 2; it++) {
        uint32_t h[4];
        h[0] = h2_bits(__floats2half2_rn(ar[it * 8 + 0], ar[it * 8 + 1]));
        h[1] = h2_bits(__floats2half2_rn(ar[it * 8 + 2], ar[it * 8 + 3]));
        h[2] = h2_bits(__floats2half2_rn(ar[it * 8 + 4], ar[it * 8 + 5]));
        h[3] = h2_bits(__floats2half2_rn(ar[it * 8 + 6], ar[it * 8 + 7]));
        uint32_t so = sA + swz((uint32_t)((it * 64 + rb) * 128 + g * 16));
        asm volatile("st.shared.v4.b32 [%0], {%1,%2,%3,%4};\n"
                     :: "r"(so), "r"(h[0]), "r"(h[1]), "r"(h[2]), "r"(h[3]));
    }
}

__device__ __forceinline__ void g1_loadB(const __half* __restrict__ B,
                                         int n0, int c, uint32_t sB, int t)
{
    const int k0 = c * 64;
    const int ch = t & 7;
    const int rb = t >> 3;           // 0..63
#pragma unroll
    for (int it = 0; it < 4; it++) {
        int r = it * 64 + rb;        // 0..255
        cp16(sB + swz((uint32_t)(r * 128 + ch * 16)),
             B + (size_t)(n0 + r) * DIM + k0 + ch * 8);
    }
}

__global__ __launch_bounds__(512, 1)
void mma_gemm1(const float* __restrict__ x, const __half* __restrict__ B,
               const float* __restrict__ bq, const float* __restrict__ bk,
               __half* __restrict__ qh, __half* __restrict__ kh)
{
    extern __shared__ char smem[];
    const uint32_t sb = smem_u32(smem);
    const int t = threadIdx.x;
    const int w = t >> 5, l = t & 31;
    const int m0 = blockIdx.y * 128;
    const int n0 = blockIdx.x * 256;

    uint32_t sA[3], sB[3];
#pragma unroll
    for (int s = 0; s < 3; s++) { sA[s] = sb + s * G1_STAGE; sB[s] = sA[s] + 16384u; }

    // prologue: chunks 0,1
    {
        float ar0[16], ar1[16];
        g1_ldgA(x, m0, 0, t, ar0);
        g1_loadB(B, n0, 0, sB[0], t); CP_COMMIT();
        g1_ldgA(x, m0, 1, t, ar1);
        g1_loadB(B, n0, 1, sB[1], t); CP_COMMIT();
        g1_cvt_sts(sA[0], t, ar0);
        g1_cvt_sts(sA[1], t, ar1);
    }

    const int wm = w & 1;          // M half (0/1) -> 64 rows
    const int wn = w >> 1;         // N eighth (0..7) -> 32 cols
    const uint32_t aBase = (uint32_t)((wm * 64 + (l & 15)) * 128 + (l >> 4) * 16);
    const uint32_t bBase = (uint32_t)((wn * 32 + ((l >> 4) * 8) + (l & 7)) * 128
                                      + ((l >> 3) & 1) * 16);

    float acc[4][4][4];
#pragma unroll
    for (int i = 0; i < 4; i++)
#pragma unroll
        for (int j = 0; j < 4; j++)
#pragma unroll
            for (int e = 0; e < 4; e++) acc[i][j][e] = 0.0f;

    for (int c = 0; c < 8; c++) {
        const int pf = c + 2;
        float ar[16];
        if (pf < 8) g1_ldgA(x, m0, pf, t, ar);   // issue early; MMA hides latency
        CP_WAIT1();
        __syncthreads();
        if (pf < 8) g1_loadB(B, n0, pf, sB[pf % 3], t);
        CP_COMMIT();

        const uint32_t cA = sA[c % 3], cB = sB[c % 3];
#pragma unroll
        for (int s = 0; s < 4; s++) {
            uint32_t a[4][4], b[4][2];
#pragma unroll
            for (int i = 0; i < 4; i++) {
                uint32_t off = aBase + i * 2048 + s * 32;
                ldsm4(a[i], cA + (off ^ ((off >> 3) & 0x70)));
            }
#pragma unroll
            for (int jj = 0; jj < 2; jj++) {
                uint32_t off = bBase + jj * 2048 + s * 32;
                uint32_t r[4];
                ldsm4(r, cB + (off ^ ((off >> 3) & 0x70)));
                b[2 * jj][0] = r[0]; b[2 * jj][1] = r[1];
                b[2 * jj + 1][0] = r[2]; b[2 * jj + 1][1] = r[3];
            }
#pragma unroll
            for (int i = 0; i < 4; i++)
#pragma unroll
                for (int j = 0; j < 4; j++)
                    mma16816(acc[i][j], a[i], b[j]);
        }
        if (pf < 8) g1_cvt_sts(sA[pf % 3], t, ar);
    }

    // ---- epilogue: n0 tiles 0..1 -> q, 2..3 -> k ----
    const float* bias = (n0 < 512) ? bq : bk;
    __half* outh      = (n0 < 512) ? qh : kh;
    const int cb = n0 & 511;

    const int colw = cb + wn * 32 + (l & 3) * 2;
    float bj[4][2];
#pragma unroll
    for (int j = 0; j < 4; j++) {
        bj[j][0] = bias[colw + j * 8];
        bj[j][1] = bias[colw + j * 8 + 1];
    }

    const int mrow = m0 + wm * 64 + (l >> 2);
#pragma unroll
    for (int i = 0; i < 4; i++) {
        int r0 = mrow + i * 16, r1 = r0 + 8;
#pragma unroll
        for (int j = 0; j < 4; j++) {
            int cc = colw + j * 8;
            size_t o0 = (size_t)r0 * DIM + cc;
            size_t o1 = (size_t)r1 * DIM + cc;
            *reinterpret_cast<__half2*>(outh + o0) =
                __floats2half2_rn(acc[i][j][0] + bj[j][0], acc[i][j][1] + bj[j][1]);
            *reinterpret_cast<__half2*>(outh + o1) =
                __floats2half2_rn(acc[i][j][2] + bj[j][0], acc[i][j][3] + bj[j][1]);
        }
    }
}

// ===========================================================================
// GEMM2/3 (proven config): fp16 A/B, CTA 128x128, 256 thr, 3-stage, occ 2.
// MODE 1: per-batch B, fp16 addend added, fp16 out
// MODE 2: fp32 out + bias
// ===========================================================================
#define STAGES 3
#define CHUNKS 8
#define GEMM_SMEM (STAGES * 32768)   // 96 KB

__device__ __forceinline__ void load_chunk(
    const __half* __restrict__ A, const __half* __restrict__ B,
    int m0, int n0, int c, uint32_t sA, uint32_t sB, int t)
{
    const int k0 = c * 64;
    const int ch = t & 7;
    const int rb = t >> 3;
#pragma unroll
    for (int it = 0; it < 4; it++) {
        int r = it * 32 + rb;
        cp16(sA + swz((uint32_t)(r * 128 + ch * 16)),
             A + (size_t)(m0 + r) * DIM + k0 + ch * 8);
    }
#pragma unroll
    for (int it = 0; it < 4; it++) {
        int r = it * 32 + rb;
        cp16(sB + swz((uint32_t)(r * 128 + ch * 16)),
             B + (size_t)(n0 + r) * DIM + k0 + ch * 8);
    }
}

template <int MODE>
__global__ __launch_bounds__(256, 2)
void mma_gemm(const __half* __restrict__ A, const __half* __restrict__ B,
              const float* __restrict__ bias0,
              const __half* __restrict__ addH,
              float* __restrict__ outF, __half* __restrict__ outH)
{
    extern __shared__ char smem[];
    const uint32_t sb = smem_u32(smem);
    const int t = threadIdx.x;
    const int w = t >> 5, l = t & 31;
    const int m0 = blockIdx.y * 128;
    const int n0 = blockIdx.x * 128;

    if (MODE == 1)
        B += (size_t)(m0 / SEQ) * DIM * DIM;

    uint32_t sA[STAGES], sB[STAGES];
#pragma unroll
    for (int s = 0; s < STAGES; s++) { sA[s] = sb + s * 32768u; sB[s] = sA[s] + 16384u; }

    load_chunk(A, B, m0, n0, 0, sA[0], sB[0], t); CP_COMMIT();
    load_chunk(A, B, m0, n0, 1, sA[1], sB[1], t); CP_COMMIT();

    const int wm = w & 1;
    const int wn = w >> 1;
    const uint32_t aBase = (uint32_t)((wm * 64 + (l & 15)) * 128 + (l >> 4) * 16);
    const uint32_t bBase = (uint32_t)((wn * 32 + ((l >> 4) * 8) + (l & 7)) * 128
                                      + ((l >> 3) & 1) * 16);

    float acc[4][4][4];
#pragma unroll
    for (int i = 0; i < 4; i++)
#pragma unroll
        for (int j = 0; j < 4; j++)
#pragma unroll
            for (int e = 0; e < 4; e++) acc[i][j][e] = 0.0f;

    for (int c = 0; c < CHUNKS; c++) {
        CP_WAIT1();
        __syncthreads();
        const int pf = c + 2;
        if (pf < CHUNKS)
            load_chunk(A, B, m0, n0, pf, sA[pf % 3], sB[pf % 3], t);
        CP_COMMIT();

        const uint32_t cA = sA[c % 3], cB = sB[c % 3];
#pragma unroll
        for (int s = 0; s < 4; s++) {
            uint32_t a[4][4], b[4][2];
#pragma unroll
            for (int i = 0; i < 4; i++) {
                uint32_t off = aBase + i * 2048 + s * 32;
                ldsm4(a[i], cA + (off ^ ((off >> 3) & 0x70)));
            }
#pragma unroll
            for (int jj = 0; jj < 2; jj++) {
                uint32_t off = bBase + jj * 2048 + s * 32;
                uint32_t r[4];
                ldsm4(r, cB + (off ^ ((off >> 3) & 0x70)));
                b[2 * jj][0] = r[0]; b[2 * jj][1] = r[1];
                b[2 * jj + 1][0] = r[2]; b[2 * jj + 1][1] = r[3];
            }
#pragma unroll
            for (int i = 0; i < 4; i++)
#pragma unroll
                for (int j = 0; j < 4; j++)
                    mma16816(acc[i][j], a[i], b[j]);
        }
    }

    const int colw = n0 + wn * 32 + (l & 3) * 2;
    float bj[4][2];
#pragma unroll
    for (int j = 0; j < 4; j++) {
        bj[j][0] = bias0[colw + j * 8];
        bj[j][1] = bias0[colw + j * 8 + 1];
    }

    const int mrow = m0 + wm * 64 + (l >> 2);
#pragma unroll
    for (int i = 0; i < 4; i++) {
        int r0 = mrow + i * 16, r1 = r0 + 8;
#pragma unroll
        for (int j = 0; j < 4; j++) {
            int cc = colw + j * 8;
            float v0 = acc[i][j][0] + bj[j][0];
            float v1 = acc[i][j][1] + bj[j][1];
            float v2 = acc[i][j][2] + bj[j][0];
            float v3 = acc[i][j][3] + bj[j][1];
            size_t o0 = (size_t)r0 * DIM + cc;
            size_t o1 = (size_t)r1 * DIM + cc;
            if (MODE == 1) {
                float2 a0 = __half22float2(*reinterpret_cast<const __half2*>(addH + o0));
                float2 a1 = __half22float2(*reinterpret_cast<const __half2*>(addH + o1));
                v0 += a0.x; v1 += a0.y; v2 += a1.x; v3 += a1.y;
                *reinterpret_cast<__half2*>(outH + o0) = __floats2half2_rn(v0, v1);
                *reinterpret_cast<__half2*>(outH + o1) = __floats2half2_rn(v2, v3);
            } else {
                *reinterpret_cast<float2*>(outF + o0) = make_float2(v0, v1);
                *reinterpret_cast<float2*>(outF + o1) = make_float2(v2, v3);
            }
        }
    }
}

// ---------------------------------------------------------------------------
// Transpose + convert one weight: th[zoff*D*D + n*D + k] = fp16(w[k][n])
// ---------------------------------------------------------------------------
__global__ void wsplit_kernel(const float* __restrict__ w,
                              __half* __restrict__ th, int zoff)
{
    __shared__ float sm[32][33];
    const int n0 = blockIdx.x * 32, k0 = blockIdx.y * 32;
    sm[threadIdx.y][threadIdx.x] = w[(size_t)(k0 + threadIdx.y) * DIM + n0 + threadIdx.x];
    __syncthreads();
    float v = sm[threadIdx.x][threadIdx.y];   // w[k0+tx][n0+ty]
    size_t o = (size_t)zoff * DIM * DIM + (size_t)(n0 + threadIdx.y) * DIM + k0 + threadIdx.x;
    th[o] = __float2half_rn(v);
}

// out[b][n][k] = fp16(gq[b][k] * wp[k][n])
__global__ void wpsplit_kernel(const float* __restrict__ wp,
                               const float* __restrict__ gq,
                               __half* __restrict__ th)
{
    __shared__ float sm[32][33];
    const int b = blockIdx.z;
    const int n0 = blockIdx.x * 32, k0 = blockIdx.y * 32;
    sm[threadIdx.y][threadIdx.x] = wp[(size_t)(k0 + threadIdx.y) * DIM + n0 + threadIdx.x];
    __syncthreads();
    float v = sm[threadIdx.x][threadIdx.y] * gq[b * DIM + k0 + threadIdx.x];
    size_t o = (size_t)b * DIM * DIM + (size_t)(n0 + threadIdx.y) * DIM + k0 + threadIdx.x;
    th[o] = __float2half_rn(v);
}

// ---------------------------------------------------------------------------
// L2-normalize q and k (fp16 in place). grid = M_TOTAL, 128 thr (4 halfs each).
// ---------------------------------------------------------------------------
__global__ void l2norm_kernel(__half* __restrict__ q, __half* __restrict__ k)
{
    const int row = blockIdx.x;
    const int tid = threadIdx.x;
    __half2* qr = reinterpret_cast<__half2*>(q + (size_t)row * DIM);
    __half2* kr = reinterpret_cast<__half2*>(k + (size_t)row * DIM);

    __half2 q0 = qr[2 * tid], q1 = qr[2 * tid + 1];
    __half2 k0 = kr[2 * tid], k1 = kr[2 * tid + 1];
    float2 qf0 = __half22float2(q0), qf1 = __half22float2(q1);
    float2 kf0 = __half22float2(k0), kf1 = __half22float2(k1);

    float sq = qf0.x * qf0.x + qf0.y * qf0.y + qf1.x * qf1.x + qf1.y * qf1.y;
    float sk = kf0.x * kf0.x + kf0.y * kf0.y + kf1.x * kf1.x + kf1.y * kf1.y;
#pragma unroll
    for (int o = 16; o > 0; o >>= 1) {
        sq += __shfl_xor_sync(0xFFFFFFFFu, sq, o);
        sk += __shfl_xor_sync(0xFFFFFFFFu, sk, o);
    }
    __shared__ float sh[8];
    const int wid = tid >> 5, lane = tid & 31;
    if (lane == 0) { sh[wid] = sq; sh[4 + wid] = sk; }
    __syncthreads();
    sq = sh[0] + sh[1] + sh[2] + sh[3];
    sk = sh[4] + sh[5] + sh[6] + sh[7];
    const float rq = rsqrtf(fmaxf(sq, 1e-12f));
    const float rk = rsqrtf(fmaxf(sk, 1e-12f));

    qr[2 * tid]     = __floats2half2_rn(qf0.x * rq, qf0.y * rq);
    qr[2 * tid + 1] = __floats2half2_rn(qf1.x * rq, qf1.y * rq);
    kr[2 * tid]     = __floats2half2_rn(kf0.x * rk, kf0.y * rk);
    kr[2 * tid + 1] = __floats2half2_rn(kf1.x * rk, kf1.y * rk);
}

__global__ void zero_gq_kernel(float* __restrict__ gq, int base)
{
    int i = base + blockIdx.x * blockDim.x + threadIdx.x;
    if (i < BATCH * DIM) gq[i] = 0.0f;
}

// gq[b,d] = sum_n qn[b,n,d]  (qn fp16). 128 threads x 4 halfs cover 512 d.
__global__ void batch_sum_kernel(const __half* __restrict__ qn, float* __restrict__ gq)
{
    const int d4 = threadIdx.x;
    const int b  = blockIdx.y;
    const int n0 = blockIdx.z * 256;
    const __half2* base = reinterpret_cast<const __half2*>(
        qn + ((size_t)b * SEQ + n0) * DIM) + 2 * d4;
    float s0 = 0.f, s1 = 0.f, s2 = 0.f, s3 = 0.f;
#pragma unroll 8
    for (int i = 0; i < 256; i++) {
        float2 v0 = __half22float2(base[(size_t)i * (DIM / 2)]);
        float2 v1 = __half22float2(base[(size_t)i * (DIM / 2) + 1]);
        s0 += v0.x; s1 += v0.y; s2 += v1.x; s3 += v1.y;
    }
    float* g = gq + b * DIM + d4 * 4;
    atomicAdd(g + 0, s0);
    atomicAdd(g + 1, s1);
    atomicAdd(g + 2, s2);
    atomicAdd(g + 3, s3);
}

// ---------------------------------------------------------------------------
extern "C" void kernel_launch(void* const* d_in, const int* in_sizes, int n_in,
                              void* d_out, int out_size)
{
    const float* x  = (const float*)d_in[0];
    const float* wq = (const float*)d_in[1];
    const float* bq = (const float*)d_in[2];
    const float* wk = (const float*)d_in[3];
    const float* bk = (const float*)d_in[4];
    const float* wp = (const float*)d_in[5];
    const float* bp = (const float*)d_in[6];
    const float* wf = (const float*)d_in[7];
    const float* bf = (const float*)d_in[8];
    // d_in[9] = w_g: softmax over size-1 axis == 1 -> unused
    float* out = (float*)d_out;

    __half *uh, *qh, *kh, *wT, *wpT;
    float *gq;
    cudaGetSymbolAddress((void**)&uh,  g_uh);
    cudaGetSymbolAddress((void**)&qh,  g_qh);
    cudaGetSymbolAddress((void**)&kh,  g_kh);
    cudaGetSymbolAddress((void**)&wT,  g_wT);
    cudaGetSymbolAddress((void**)&wpT, g_wpT);
    cudaGetSymbolAddress((void**)&gq,  g_gq);

    cudaFuncSetAttribute(mma_gemm1, cudaFuncAttributeMaxDynamicSharedMemorySize, G1_SMEM);
    cudaFuncSetAttribute(mma_gemm<1>, cudaFuncAttributeMaxDynamicSharedMemorySize, GEMM_SMEM);
    cudaFuncSetAttribute(mma_gemm<2>, cudaFuncAttributeMaxDynamicSharedMemorySize, GEMM_SMEM);

    const int MT = M_TOTAL / 128;   // 256 row tiles

    // launches 0-4 (prep; GEMM1 is launch index 5 for ncu -s 5 -c 1)
    wsplit_kernel<<<dim3(16, 16), dim3(32, 32)>>>(wq, wT, 0);
    wsplit_kernel<<<dim3(16, 16), dim3(32, 32)>>>(wk, wT, 1);
    wsplit_kernel<<<dim3(16, 16), dim3(32, 32)>>>(wf, wT, 2);
    zero_gq_kernel<<<8, 256>>>(gq, 0);
    zero_gq_kernel<<<8, 256>>>(gq, 2048);

    // launch 5: fused conversion + q,k GEMM (B rows 0..511 wq^T, 512..1023 wk^T)
    mma_gemm1<<<dim3(4, MT), 512, G1_SMEM>>>(x, wT, bq, bk, qh, kh);

    // normalize (fp16 in place)
    l2norm_kernel<<<M_TOTAL, 128>>>(qh, kh);
    // gq = per-batch sum of qn
    batch_sum_kernel<<<dim3(1, BATCH, SEQ / 256), 128>>>(qh, gq);
    // per-batch scaled wp (transposed, fp16)
    wpsplit_kernel<<<dim3(16, 16, BATCH), dim3(32, 32)>>>(wp, gq, wpT);

    // u = kn @ (diag(gq_b) wp) + bp + qn  -> fp16
    mma_gemm<1><<<dim3(4, MT), 256, GEMM_SMEM>>>(kh, wpT, bp, qh, nullptr, uh);
    // out = u @ wf + bf
    mma_gemm<2><<<dim3(4, MT), 256, GEMM_SMEM>>>(uh, wT + 2u * DIM * DIM, bf,
                                                 nullptr, out, nullptr);
}

// round 11
// speedup vs baseline: 1.1404x; 1.1404x over previous
#include <cuda_runtime.h>
#include <cuda_fp16.h>
#include <cstdint>
#include <cstddef>

#define DIM     512
#define BATCH   8
#define SEQ     4096
#define M_TOTAL (BATCH * SEQ)   // 32768

// ---------------------------------------------------------------------------
// Scratch (__device__ globals; no allocation allowed)
// ---------------------------------------------------------------------------
__device__ __half  g_xh[(size_t)M_TOTAL * DIM];   // x fp16  -> later u fp16
__device__ __half  g_qh[(size_t)M_TOTAL * DIM];   // q -> qn (fp16, in place)
__device__ __half  g_kh[(size_t)M_TOTAL * DIM];   // k -> kn (fp16, in place)
__device__ __half  g_wT[3u * DIM * DIM];          // wq^T, wk^T, wf^T fp16 (concat rows)
__device__ __half  g_wpT[(size_t)BATCH * DIM * DIM]; // (diag(gq_b) wp)^T fp16
__device__ float   g_gq[BATCH * DIM];

// ---------------------------------------------------------------------------
// helpers
// ---------------------------------------------------------------------------
__device__ __forceinline__ uint32_t smem_u32(const void* p) {
    uint32_t a;
    asm("{ .reg .u64 t; cvta.to.shared.u64 t, %1; cvt.u32.u64 %0, t; }" : "=r"(a) : "l"(p));
    return a;
}
__device__ __forceinline__ uint32_t swz(uint32_t o) { return o ^ ((o >> 3) & 0x70); }

__device__ __forceinline__ void cp16(uint32_t s, const void* g) {
    asm volatile("cp.async.cg.shared.global [%0], [%1], 16;\n" :: "r"(s), "l"(g));
}
#define CP_COMMIT() asm volatile("cp.async.commit_group;\n" ::: "memory")
#define CP_WAIT1()  asm volatile("cp.async.wait_group 1;\n" ::: "memory")

__device__ __forceinline__ void ldsm4(uint32_t* r, uint32_t addr) {
    asm volatile("ldmatrix.sync.aligned.m8n8.x4.shared.b16 {%0,%1,%2,%3}, [%4];\n"
                 : "=r"(r[0]), "=r"(r[1]), "=r"(r[2]), "=r"(r[3]) : "r"(addr));
}
__device__ __forceinline__ void mma16816(float* d, const uint32_t* a, const uint32_t* b) {
    asm volatile(
        "mma.sync.aligned.m16n8k16.row.col.f32.f16.f16.f32 "
        "{%0,%1,%2,%3}, {%4,%5,%6,%7}, {%8,%9}, {%0,%1,%2,%3};\n"
        : "+f"(d[0]), "+f"(d[1]), "+f"(d[2]), "+f"(d[3])
        : "r"(a[0]), "r"(a[1]), "r"(a[2]), "r"(a[3]), "r"(b[0]), "r"(b[1]));
}

// ---------------------------------------------------------------------------
// fp16 GEMM (proven config): CTA 128x128, 256 thr, 3-stage cp.async, occ 2.
// MODE 0: two fp16 outputs (cols <512 -> out0h/bias0, >=512 -> out1h/bias1)
// MODE 1: per-batch B, fp16 addend added, fp16 out0h
// MODE 2: fp32 out + bias0
// ---------------------------------------------------------------------------
#define STAGES 3
#define CHUNKS 8
#define GEMM_SMEM (STAGES * 32768)   // 96 KB

__device__ __forceinline__ void load_chunk(
    const __half* __restrict__ A, const __half* __restrict__ B,
    int m0, int n0, int c, uint32_t sA, uint32_t sB, int t)
{
    const int k0 = c * 64;
    const int ch = t & 7;          // 16B chunk within 128B row
    const int rb = t >> 3;         // 0..31
#pragma unroll
    for (int it = 0; it < 4; it++) {
        int r = it * 32 + rb;
        cp16(sA + swz((uint32_t)(r * 128 + ch * 16)),
             A + (size_t)(m0 + r) * DIM + k0 + ch * 8);
    }
#pragma unroll
    for (int it = 0; it < 4; it++) {
        int r = it * 32 + rb;
        cp16(sB + swz((uint32_t)(r * 128 + ch * 16)),
             B + (size_t)(n0 + r) * DIM + k0 + ch * 8);
    }
}

template <int MODE>
__global__ __launch_bounds__(256, 2)
void mma_gemm(const __half* __restrict__ A, const __half* __restrict__ B,
              const float* __restrict__ bias0, const float* __restrict__ bias1,
              const __half* __restrict__ addH,
              float* __restrict__ outF,
              __half* __restrict__ out0h, __half* __restrict__ out1h)
{
    extern __shared__ char smem[];
    const uint32_t sb = smem_u32(smem);
    const int t = threadIdx.x;
    const int w = t >> 5, l = t & 31;
    const int m0 = blockIdx.y * 128;
    const int n0 = blockIdx.x * 128;

    if (MODE == 1)
        B += (size_t)(m0 / SEQ) * DIM * DIM;

    uint32_t sA[STAGES], sB[STAGES];
#pragma unroll
    for (int s = 0; s < STAGES; s++) { sA[s] = sb + s * 32768u; sB[s] = sA[s] + 16384u; }

    load_chunk(A, B, m0, n0, 0, sA[0], sB[0], t); CP_COMMIT();
    load_chunk(A, B, m0, n0, 1, sA[1], sB[1], t); CP_COMMIT();

    const int wm = w & 1;          // M half (0/1) -> 64 rows
    const int wn = w >> 1;         // N quarter (0..3) -> 32 cols
    const uint32_t aBase = (uint32_t)((wm * 64 + (l & 15)) * 128 + (l >> 4) * 16);
    const uint32_t bBase = (uint32_t)((wn * 32 + ((l >> 4) * 8) + (l & 7)) * 128
                                      + ((l >> 3) & 1) * 16);

    float acc[4][4][4];
#pragma unroll
    for (int i = 0; i < 4; i++)
#pragma unroll
        for (int j = 0; j < 4; j++)
#pragma unroll
            for (int e = 0; e < 4; e++) acc[i][j][e] = 0.0f;

    for (int c = 0; c < CHUNKS; c++) {
        CP_WAIT1();
        __syncthreads();
        const int pf = c + 2;
        if (pf < CHUNKS)
            load_chunk(A, B, m0, n0, pf, sA[pf % 3], sB[pf % 3], t);
        CP_COMMIT();

        const uint32_t cA = sA[c % 3], cB = sB[c % 3];
#pragma unroll
        for (int s = 0; s < 4; s++) {
            uint32_t a[4][4], b[4][2];
#pragma unroll
            for (int i = 0; i < 4; i++) {
                uint32_t off = aBase + i * 2048 + s * 32;
                ldsm4(a[i], cA + (off ^ ((off >> 3) & 0x70)));
            }
#pragma unroll
            for (int jj = 0; jj < 2; jj++) {
                uint32_t off = bBase + jj * 2048 + s * 32;
                uint32_t r[4];
                ldsm4(r, cB + (off ^ ((off >> 3) & 0x70)));
                b[2 * jj][0] = r[0]; b[2 * jj][1] = r[1];
                b[2 * jj + 1][0] = r[2]; b[2 * jj + 1][1] = r[3];
            }
#pragma unroll
            for (int i = 0; i < 4; i++)
#pragma unroll
                for (int j = 0; j < 4; j++)
                    mma16816(acc[i][j], a[i], b[j]);
        }
    }

    // ---- epilogue ----
    const float* bias = bias0;
    __half* outh = out0h;
    int cb = n0;
    if (MODE == 0 && n0 >= 512) { bias = bias1; outh = out1h; cb = n0 - 512; }

    const int colw = cb + wn * 32 + (l & 3) * 2;
    float bj[4][2];
#pragma unroll
    for (int j = 0; j < 4; j++) {
        bj[j][0] = bias[colw + j * 8];
        bj[j][1] = bias[colw + j * 8 + 1];
    }

    const int mrow = m0 + wm * 64 + (l >> 2);
#pragma unroll
    for (int i = 0; i < 4; i++) {
        int r0 = mrow + i * 16, r1 = r0 + 8;
#pragma unroll
        for (int j = 0; j < 4; j++) {
            int cc = colw + j * 8;
            float v0 = acc[i][j][0] + bj[j][0];
            float v1 = acc[i][j][1] + bj[j][1];
            float v2 = acc[i][j][2] + bj[j][0];
            float v3 = acc[i][j][3] + bj[j][1];
            size_t o0 = (size_t)r0 * DIM + cc;
            size_t o1 = (size_t)r1 * DIM + cc;
            if (MODE == 1) {
                float2 a0 = __half22float2(*reinterpret_cast<const __half2*>(addH + o0));
                float2 a1 = __half22float2(*reinterpret_cast<const __half2*>(addH + o1));
                v0 += a0.x; v1 += a0.y; v2 += a1.x; v3 += a1.y;
            }
            if (MODE == 2) {
                *reinterpret_cast<float2*>(outF + o0) = make_float2(v0, v1);
                *reinterpret_cast<float2*>(outF + o1) = make_float2(v2, v3);
            } else {
                *reinterpret_cast<__half2*>(outh + o0) = __floats2half2_rn(v0, v1);
                *reinterpret_cast<__half2*>(outh + o1) = __floats2half2_rn(v2, v3);
            }
        }
    }
}

// ---------------------------------------------------------------------------
// x -> fp16 (partial grid; base = float4 offset)
// ---------------------------------------------------------------------------
__global__ void cvt_x_kernel(const float* __restrict__ x, __half* __restrict__ h,
                             size_t base)
{
    size_t i = base + (size_t)blockIdx.x * blockDim.x + threadIdx.x;   // float4 index
    float4 v = reinterpret_cast<const float4*>(x)[i];
    reinterpret_cast<__half2*>(h)[2 * i]     = __floats2half2_rn(v.x, v.y);
    reinterpret_cast<__half2*>(h)[2 * i + 1] = __floats2half2_rn(v.z, v.w);
}

// ---------------------------------------------------------------------------
// Transpose + convert one weight: th[zoff*D*D + n*D + k] = fp16(w[k][n])
// ---------------------------------------------------------------------------
__global__ void wsplit_kernel(const float* __restrict__ w,
                              __half* __restrict__ th, int zoff)
{
    __shared__ float sm[32][33];
    const int n0 = blockIdx.x * 32, k0 = blockIdx.y * 32;
    sm[threadIdx.y][threadIdx.x] = w[(size_t)(k0 + threadIdx.y) * DIM + n0 + threadIdx.x];
    __syncthreads();
    float v = sm[threadIdx.x][threadIdx.y];   // w[k0+tx][n0+ty]
    size_t o = (size_t)zoff * DIM * DIM + (size_t)(n0 + threadIdx.y) * DIM + k0 + threadIdx.x;
    th[o] = __float2half_rn(v);
}

// out[b][n][k] = fp16(gq[b][k] * wp[k][n])
__global__ void wpsplit_kernel(const float* __restrict__ wp,
                               const float* __restrict__ gq,
                               __half* __restrict__ th)
{
    __shared__ float sm[32][33];
    const int b = blockIdx.z;
    const int n0 = blockIdx.x * 32, k0 = blockIdx.y * 32;
    sm[threadIdx.y][threadIdx.x] = wp[(size_t)(k0 + threadIdx.y) * DIM + n0 + threadIdx.x];
    __syncthreads();
    float v = sm[threadIdx.x][threadIdx.y] * gq[b * DIM + k0 + threadIdx.x];
    size_t o = (size_t)b * DIM * DIM + (size_t)(n0 + threadIdx.y) * DIM + k0 + threadIdx.x;
    th[o] = __float2half_rn(v);
}

// ---------------------------------------------------------------------------
// L2-normalize q and k (fp16 in place), warp-per-row, no smem/block barrier.
// 256 threads = 8 warps = 8 rows per block; lane holds 16 halfs per array.
// ---------------------------------------------------------------------------
__device__ __forceinline__ float ss_acc(uint4 v) {
    const __half2* h = reinterpret_cast<const __half2*>(&v);
    float s = 0.f;
#pragma unroll
    for (int i = 0; i < 4; i++) {
        float2 f = __half22float2(h[i]);
        s += f.x * f.x + f.y * f.y;
    }
    return s;
}
__device__ __forceinline__ uint4 scale4(uint4 v, float r) {
    __half2* h = reinterpret_cast<__half2*>(&v);
#pragma unroll
    for (int i = 0; i < 4; i++) {
        float2 f = __half22float2(h[i]);
        h[i] = __floats2half2_rn(f.x * r, f.y * r);
    }
    return v;
}

__global__ void l2norm_kernel(__half* __restrict__ q, __half* __restrict__ k)
{
    const int lane = threadIdx.x & 31;
    const int wid  = threadIdx.x >> 5;
    const int row  = blockIdx.x * 8 + wid;

    uint4* qp = reinterpret_cast<uint4*>(q + (size_t)row * DIM);
    uint4* kp = reinterpret_cast<uint4*>(k + (size_t)row * DIM);
    uint4 q0 = qp[2 * lane], q1 = qp[2 * lane + 1];
    uint4 k0 = kp[2 * lane], k1 = kp[2 * lane + 1];

    float sq = ss_acc(q0) + ss_acc(q1);
    float sk = ss_acc(k0) + ss_acc(k1);
#pragma unroll
    for (int o = 16; o > 0; o >>= 1) {
        sq += __shfl_xor_sync(0xFFFFFFFFu, sq, o);
        sk += __shfl_xor_sync(0xFFFFFFFFu, sk, o);
    }
    const float rq = rsqrtf(fmaxf(sq, 1e-12f));
    const float rk = rsqrtf(fmaxf(sk, 1e-12f));

    qp[2 * lane]     = scale4(q0, rq);
    qp[2 * lane + 1] = scale4(q1, rq);
    kp[2 * lane]     = scale4(k0, rk);
    kp[2 * lane + 1] = scale4(k1, rk);
}

__global__ void zero_gq_kernel(float* __restrict__ gq)
{
    int i = blockIdx.x * blockDim.x + threadIdx.x;
    if (i < BATCH * DIM) gq[i] = 0.0f;
}

// gq[b,d] = sum_n qn[b,n,d]  (qn fp16). 128 threads x 4 halfs cover 512 d.
__global__ void batch_sum_kernel(const __half* __restrict__ qn, float* __restrict__ gq)
{
    const int d4 = threadIdx.x;
    const int b  = blockIdx.y;
    const int n0 = blockIdx.z * 256;
    const __half2* base = reinterpret_cast<const __half2*>(
        qn + ((size_t)b * SEQ + n0) * DIM) + 2 * d4;
    float s0 = 0.f, s1 = 0.f, s2 = 0.f, s3 = 0.f;
#pragma unroll 8
    for (int i = 0; i < 256; i++) {
        float2 v0 = __half22float2(base[(size_t)i * (DIM / 2)]);
        float2 v1 = __half22float2(base[(size_t)i * (DIM / 2) + 1]);
        s0 += v0.x; s1 += v0.y; s2 += v1.x; s3 += v1.y;
    }
    float* g = gq + b * DIM + d4 * 4;
    atomicAdd(g + 0, s0);
    atomicAdd(g + 1, s1);
    atomicAdd(g + 2, s2);
    atomicAdd(g + 3, s3);
}

// ---------------------------------------------------------------------------
extern "C" void kernel_launch(void* const* d_in, const int* in_sizes, int n_in,
                              void* d_out, int out_size)
{
    const float* x  = (const float*)d_in[0];
    const float* wq = (const float*)d_in[1];
    const float* bq = (const float*)d_in[2];
    const float* wk = (const float*)d_in[3];
    const float* bk = (const float*)d_in[4];
    const float* wp = (const float*)d_in[5];
    const float* bp = (const float*)d_in[6];
    const float* wf = (const float*)d_in[7];
    const float* bf = (const float*)d_in[8];
    // d_in[9] = w_g: softmax over size-1 axis == 1 -> unused
    float* out = (float*)d_out;

    __half *xh, *qh, *kh, *wT, *wpT;
    float *gq;
    cudaGetSymbolAddress((void**)&xh,  g_xh);
    cudaGetSymbolAddress((void**)&qh,  g_qh);
    cudaGetSymbolAddress((void**)&kh,  g_kh);
    cudaGetSymbolAddress((void**)&wT,  g_wT);
    cudaGetSymbolAddress((void**)&wpT, g_wpT);
    cudaGetSymbolAddress((void**)&gq,  g_gq);

    cudaFuncSetAttribute(mma_gemm<0>, cudaFuncAttributeMaxDynamicSharedMemorySize, GEMM_SMEM);
    cudaFuncSetAttribute(mma_gemm<1>, cudaFuncAttributeMaxDynamicSharedMemorySize, GEMM_SMEM);
    cudaFuncSetAttribute(mma_gemm<2>, cudaFuncAttributeMaxDynamicSharedMemorySize, GEMM_SMEM);

    const int MT = M_TOTAL / 128;            // 256 row tiles
    const size_t NV4 = (size_t)M_TOTAL * DIM / 4;   // float4 count

    // launches 0-4 (prep; GEMM1 is launch index 5 for ncu -s 5 -c 1)
    cvt_x_kernel<<<NV4 / 2 / 256, 256>>>(x, xh, 0);
    cvt_x_kernel<<<NV4 / 2 / 256, 256>>>(x, xh, NV4 / 2);
    wsplit_kernel<<<dim3(16, 16), dim3(32, 32)>>>(wq, wT, 0);
    wsplit_kernel<<<dim3(16, 16), dim3(32, 32)>>>(wk, wT, 1);
    wsplit_kernel<<<dim3(16, 16), dim3(32, 32)>>>(wf, wT, 2);

    // launch 5 (ncu target): fused q,k GEMM. B rows 0..511 = wq^T, 512..1023 = wk^T
    mma_gemm<0><<<dim3(8, MT), 256, GEMM_SMEM>>>(xh, wT, bq, bk,
                                                 nullptr, nullptr, qh, kh);
    // zero gq accumulator
    zero_gq_kernel<<<(BATCH * DIM + 255) / 256, 256>>>(gq);
    // normalize (fp16 in place, warp per row)
    l2norm_kernel<<<M_TOTAL / 8, 256>>>(qh, kh);
    // gq = per-batch sum of qn
    batch_sum_kernel<<<dim3(1, BATCH, SEQ / 256), 128>>>(qh, gq);
    // per-batch scaled wp (transposed, fp16)
    wpsplit_kernel<<<dim3(16, 16, BATCH), dim3(32, 32)>>>(wp, gq, wpT);

    // u = kn @ (diag(gq_b) wp) + bp + qn  -> fp16 into xh (x no longer needed)
    mma_gemm<1><<<dim3(4, MT), 256, GEMM_SMEM>>>(kh, wpT, bp, nullptr,
                                                 qh, nullptr, xh, nullptr);
    // out = u @ wf + bf
    mma_gemm<2><<<dim3(4, MT), 256, GEMM_SMEM>>>(xh, wT + 2u * DIM * DIM, bf, nullptr,
                                                 nullptr, out, nullptr, nullptr);
}